// round 11
// baseline (speedup 1.0000x reference)
#include <cuda_runtime.h>
#include <cuda_bf16.h>
#include <math.h>

#define Bsz 8
#define Lseq 2048
#define Dd 128
#define NROWS (Bsz * Lseq)
#define BLD (NROWS * Dd)
#define BDD (Bsz * Dd * Dd)
#define NG 16
#define SP 136

__device__ float g_qkv[NROWS * 512];
__device__ float g_g  [NROWS * 256];
__device__ float g_pk [NROWS * 640];
__device__ float g_res[NROWS * Dd];
__device__ float g_out[NROWS * Dd];
__device__ float g_ol [NROWS * Dd];
__device__ float g_part[NROWS * NG * Dd];

__device__ __forceinline__ float sigf(float x) { return 1.f / (1.f + __expf(-x)); }

__device__ __forceinline__ float warp_sum(float x) {
#pragma unroll
    for (int o = 16; o >= 1; o >>= 1) x += __shfl_xor_sync(0xffffffffu, x, o);
    return x;
}

template <bool SIG>
__global__ void __launch_bounds__(256) gemm_kernel(const float* __restrict__ A, int lda,
                                                   const float* __restrict__ W,
                                                   float* __restrict__ C, int ldc) {
    __shared__ float As[64][17];
    __shared__ float Ws[64][17];
    int bx = blockIdx.x, by = blockIdx.y, tid = threadIdx.x;
    int tx = tid & 15, ty = tid >> 4;
    int lr = tid >> 2, lk0 = (tid & 3) * 4;

    float acc[4][4];
#pragma unroll
    for (int m = 0; m < 4; m++)
#pragma unroll
        for (int n = 0; n < 4; n++) acc[m][n] = 0.f;

    const float* Arow = A + (size_t)(by * 64 + lr) * lda;
    const float* Wrow = W + (size_t)(bx * 64 + lr) * 128;

#pragma unroll 1
    for (int kt = 0; kt < 8; kt++) {
        int k0 = kt * 16;
        float4 av = *reinterpret_cast<const float4*>(Arow + k0 + lk0);
        float4 wv = *reinterpret_cast<const float4*>(Wrow + k0 + lk0);
        As[lr][lk0 + 0] = av.x; As[lr][lk0 + 1] = av.y;
        As[lr][lk0 + 2] = av.z; As[lr][lk0 + 3] = av.w;
        Ws[lr][lk0 + 0] = wv.x; Ws[lr][lk0 + 1] = wv.y;
        Ws[lr][lk0 + 2] = wv.z; Ws[lr][lk0 + 3] = wv.w;
        __syncthreads();
#pragma unroll
        for (int kk = 0; kk < 16; kk++) {
            float a[4], w[4];
#pragma unroll
            for (int m = 0; m < 4; m++) a[m] = As[ty + 16 * m][kk];
#pragma unroll
            for (int n = 0; n < 4; n++) w[n] = Ws[tx + 16 * n][kk];
#pragma unroll
            for (int m = 0; m < 4; m++)
#pragma unroll
                for (int n = 0; n < 4; n++) acc[m][n] = fmaf(a[m], w[n], acc[m][n]);
        }
        __syncthreads();
    }
#pragma unroll
    for (int m = 0; m < 4; m++) {
        int row = by * 64 + ty + 16 * m;
#pragma unroll
        for (int n = 0; n < 4; n++) {
            int col = bx * 64 + tx + 16 * n;
            float v = acc[m][n];
            if (SIG) v = sigf(v);
            C[(size_t)row * ldc + col] = v;
        }
    }
}

__global__ void __launch_bounds__(128) convpack_kernel(const float* __restrict__ qw,
                                                       const float* __restrict__ qb,
                                                       const float* __restrict__ kw,
                                                       const float* __restrict__ kb) {
    int n = blockIdx.x;
    int l = n & (Lseq - 1);
    int d = threadIdx.x;
    int lane = d & 31, w = d >> 5;
    __shared__ float redq[4], redk[4];

    const float* row = g_qkv + (size_t)n * 512;
    float qm = (l > 0)        ? row[-512 + d] : 0.f;
    float qc = row[d];
    float qp = (l < Lseq - 1) ? row[512 + d] : 0.f;
    float yq = fmaf(qw[d * 3 + 0], qm, fmaf(qw[d * 3 + 1], qc, fmaf(qw[d * 3 + 2], qp, qb[d])));
    float sq = sigf(yq);
    float km = (l > 0)        ? row[-512 + 128 + d] : 0.f;
    float kc = row[128 + d];
    float kp = (l < Lseq - 1) ? row[512 + 128 + d] : 0.f;
    float yk = fmaf(kw[d * 3 + 0], km, fmaf(kw[d * 3 + 1], kc, fmaf(kw[d * 3 + 2], kp, kb[d])));
    float sk = sigf(yk);

    float ssq = warp_sum(sq * sq);
    float ssk = warp_sum(sk * sk);
    if (lane == 0) { redq[w] = ssq; redk[w] = ssk; }
    __syncthreads();
    float nq = sqrtf(redq[0] + redq[1] + redq[2] + redq[3]);
    float nk = sqrtf(redk[0] + redk[1] + redk[2] + redk[3]);
    float qn = sq / fmaxf(nq, 1e-12f);
    float kn = sk / fmaxf(nk, 1e-12f);

    float* out = g_pk + (size_t)n * 640;
    out[d]       = qn;
    out[128 + d] = kn;
    out[256 + d] = row[256 + d];
    out[384 + d] = g_g[(size_t)n * 256 + d];
    out[512 + d] = g_g[(size_t)n * 256 + 128 + d];
}

// row-parallel scan, two-step windows: 2 butterflies + 1 state-FMA per step
__global__ void __launch_bounds__(256, 1) scan_kernel(const float* __restrict__ state,
                                                      float* __restrict__ sfin) {
    __shared__ float acc[8][8][SP];
    int b = blockIdx.x >> 4;
    int g = blockIdx.x & 15;
    int tid = threadIdx.x;
    int w = tid >> 5;
    int lane = tid & 31;
    int i = g * 8 + w;
    int j0 = lane * 4;

    float4 s = *reinterpret_cast<const float4*>(state + ((size_t)b * Dd + i) * Dd + j0);

    const float* pkb = g_pk + (size_t)b * Lseq * 640;
    float* partb = g_part + ((size_t)b * Lseq * NG + g) * Dd;

    float4 K[4], Aa[4], Bb[4];
    float Q[4], V[4];
#pragma unroll
    for (int pz = 0; pz < 4; pz++) {
        const float* pp = pkb + (size_t)pz * 640;
        K[pz]  = *reinterpret_cast<const float4*>(pp + 128 + j0);
        Aa[pz] = *reinterpret_cast<const float4*>(pp + 384 + j0);
        Bb[pz] = *reinterpret_cast<const float4*>(pp + 512 + j0);
        Q[pz] = pp[i];
        V[pz] = pp[256 + i];
    }

    // bootstrap Sk_0
    float Sk;
    {
        float pr = s.x * K[0].x;
        pr = fmaf(s.y, K[0].y, pr);
        pr = fmaf(s.z, K[0].z, pr);
        pr = fmaf(s.w, K[0].w, pr);
        Sk = warp_sum(pr);
    }

#pragma unroll 1
    for (int t0 = 0; t0 < Lseq; t0 += 4) {
#pragma unroll
        for (int wi = 0; wi < 2; wi++) {
            int t = t0 + wi * 2;
            int p0 = t & 3, p1 = (t + 1) & 3, p2 = (t + 2) & 3;
            int slot0 = (t0 & 4) | (wi * 2);

            float4 k0 = K[p0], a0 = Aa[p0], b0 = Bb[p0];
            float q0 = Q[p0], v0 = V[p0];
            float4 k1 = K[p1], a1 = Aa[p1], b1 = Bb[p1];
            float q1 = Q[p1], v1 = V[p1];
            float4 k2 = K[p2];

            // refill ring slots p0,p1 with steps t+4, t+5 (clamped)
            {
                int tz0 = t + 4 < Lseq ? t + 4 : Lseq - 1;
                int tz1 = t + 5 < Lseq ? t + 5 : Lseq - 1;
                const float* pn0 = pkb + (size_t)tz0 * 640;
                const float* pn1 = pkb + (size_t)tz1 * 640;
                K[p0]  = *reinterpret_cast<const float4*>(pn0 + 128 + j0);
                Aa[p0] = *reinterpret_cast<const float4*>(pn0 + 384 + j0);
                Bb[p0] = *reinterpret_cast<const float4*>(pn0 + 512 + j0);
                Q[p0] = pn0[i];
                V[p0] = pn0[256 + i];
                K[p1]  = *reinterpret_cast<const float4*>(pn1 + 128 + j0);
                Aa[p1] = *reinterpret_cast<const float4*>(pn1 + 384 + j0);
                Bb[p1] = *reinterpret_cast<const float4*>(pn1 + 512 + j0);
                Q[p1] = pn1[i];
                V[p1] = pn1[256 + i];
            }

            // step t elementwise:  x = a0*s + v0*bk0 ; s_t = x - ej0*Sk
            float bk0x = b0.x * k0.x, bk0y = b0.y * k0.y, bk0z = b0.z * k0.z, bk0w = b0.w * k0.w;
            float ej0x = a0.x * bk0x, ej0y = a0.y * bk0y, ej0z = a0.z * bk0z, ej0w = a0.w * bk0w;
            float xx = fmaf(a0.x, s.x, v0 * bk0x);
            float xy = fmaf(a0.y, s.y, v0 * bk0y);
            float xz = fmaf(a0.z, s.z, v0 * bk0z);
            float xw = fmaf(a0.w, s.w, v0 * bk0w);
            float stx = fmaf(-ej0x, Sk, xx);
            float sty = fmaf(-ej0y, Sk, xy);
            float stz = fmaf(-ej0z, Sk, xz);
            float stw = fmaf(-ej0w, Sk, xw);

            // step t+1 elementwise:  y = a1*s_t + v1*bk1
            float bk1x = b1.x * k1.x, bk1y = b1.y * k1.y, bk1z = b1.z * k1.z, bk1w = b1.w * k1.w;
            float ej1x = a1.x * bk1x, ej1y = a1.y * bk1y, ej1z = a1.z * bk1z, ej1w = a1.w * bk1w;
            float yx = fmaf(a1.x, stx, v1 * bk1x);
            float yy = fmaf(a1.y, sty, v1 * bk1y);
            float yz = fmaf(a1.z, stz, v1 * bk1z);
            float yw = fmaf(a1.w, stw, v1 * bk1w);

            // dots: D=k1.x, B=k1.ej0, Y=k2.y, B2=k2.ej1
            float pD = xx * k1.x;  pD = fmaf(xy, k1.y, pD);
            pD = fmaf(xz, k1.z, pD); pD = fmaf(xw, k1.w, pD);
            float pB = ej0x * k1.x; pB = fmaf(ej0y, k1.y, pB);
            pB = fmaf(ej0z, k1.z, pB); pB = fmaf(ej0w, k1.w, pB);
            float pY = yx * k2.x;  pY = fmaf(yy, k2.y, pY);
            pY = fmaf(yz, k2.z, pY); pY = fmaf(yw, k2.w, pY);
            float pB2 = ej1x * k2.x; pB2 = fmaf(ej1y, k2.y, pB2);
            pB2 = fmaf(ej1z, k2.z, pB2); pB2 = fmaf(ej1w, k2.w, pB2);

            // output for step t
            *reinterpret_cast<float4*>(&acc[slot0][w][j0]) =
                make_float4(q0 * stx, q0 * sty, q0 * stz, q0 * stw);

            // 4 interleaved butterflies
#pragma unroll
            for (int o = 16; o >= 1; o >>= 1) {
                pD  += __shfl_xor_sync(0xffffffffu, pD, o);
                pB  += __shfl_xor_sync(0xffffffffu, pB, o);
                pY  += __shfl_xor_sync(0xffffffffu, pY, o);
                pB2 += __shfl_xor_sync(0xffffffffu, pB2, o);
            }

            float Sk1 = fmaf(-Sk, pB, pD);     // Sk_{t+1}
            float Sk2 = fmaf(-Sk1, pB2, pY);   // Sk_{t+2}

            // s_{t+1} = y - ej1*Sk1 ; output for step t+1
            s.x = fmaf(-ej1x, Sk1, yx);
            s.y = fmaf(-ej1y, Sk1, yy);
            s.z = fmaf(-ej1z, Sk1, yz);
            s.w = fmaf(-ej1w, Sk1, yw);
            *reinterpret_cast<float4*>(&acc[slot0 + 1][w][j0]) =
                make_float4(q1 * s.x, q1 * s.y, q1 * s.z, q1 * s.w);

            Sk = Sk2;
        }

        __syncthreads();

        {
            int rtt  = tid >> 6;
            int rcol = tid & 63;
            int slot = (t0 & 4) | rtt;
            float r0 = 0.f, r1 = 0.f;
#pragma unroll
            for (int rr = 0; rr < 8; rr++) {
                r0 += acc[slot][rr][rcol];
                r1 += acc[slot][rr][rcol + 64];
            }
            float* dst = partb + (size_t)(t0 + rtt) * NG * Dd;
            dst[rcol]      = r0;
            dst[rcol + 64] = r1;
        }
    }

    if (sfin)
        *reinterpret_cast<float4*>(sfin + ((size_t)b * Dd + i) * Dd + j0) = s;
}

__global__ void __launch_bounds__(128) reduce_silu_kernel() {
    int n = blockIdx.x;
    int j = threadIdx.x;
    const float* base = g_part + (size_t)n * NG * Dd + j;
    float r = 0.f;
#pragma unroll
    for (int g = 0; g < NG; g++) r += base[g * Dd];
    g_out[(size_t)n * Dd + j] = r * sigf(r);
}

__global__ void __launch_bounds__(128) rms_kernel(const float* __restrict__ rmsw,
                                                  float* __restrict__ out) {
    int n = blockIdx.x;
    int d = threadIdx.x;
    int lane = d & 31, w = d >> 5;
    __shared__ float red[4];
    float v = g_ol[(size_t)n * Dd + d];
    float ss = warp_sum(v * v);
    if (lane == 0) red[w] = ss;
    __syncthreads();
    float mean = (red[0] + red[1] + red[2] + red[3]) * (1.f / 128.f);
    float s = rsqrtf(mean + 1e-6f);
    out[(size_t)n * Dd + d] = v * s * rmsw[d] + g_res[(size_t)n * Dd + d];
}

extern "C" void kernel_launch(void* const* d_in, const int* in_sizes, int n_in,
                              void* d_out, int out_size) {
    const float* x      = (const float*)d_in[0];
    const float* state  = (const float*)d_in[1];
    const float* W_in   = (const float*)d_in[2];
    const float* W_gate = (const float*)d_in[3];
    const float* W_out  = (const float*)d_in[4];
    const float* W_res  = (const float*)d_in[5];
    const float* qconvw = (const float*)d_in[6];
    const float* qconvb = (const float*)d_in[7];
    const float* kconvw = (const float*)d_in[8];
    const float* kconvb = (const float*)d_in[9];
    const float* rmsw   = (const float*)d_in[10];
    float* out = (float*)d_out;

    float *qkv, *gg, *res, *outs, *ol;
    cudaGetSymbolAddress((void**)&qkv,  g_qkv);
    cudaGetSymbolAddress((void**)&gg,   g_g);
    cudaGetSymbolAddress((void**)&res,  g_res);
    cudaGetSymbolAddress((void**)&outs, g_out);
    cudaGetSymbolAddress((void**)&ol,   g_ol);

    float* sfin = (out_size >= BLD + BDD) ? (out + BLD) : nullptr;

    gemm_kernel<false><<<dim3(512 / 64, NROWS / 64), 256>>>(x, Dd, W_in, qkv, 512);
    gemm_kernel<true><<<dim3(256 / 64, NROWS / 64), 256>>>(qkv + 384, 512, W_gate, gg, 256);
    convpack_kernel<<<NROWS, 128>>>(qconvw, qconvb, kconvw, kconvb);
    scan_kernel<<<Bsz * NG, 256>>>(state, sfin);
    gemm_kernel<false><<<dim3(Dd / 64, NROWS / 64), 256>>>(x, Dd, W_res, res, Dd);
    reduce_silu_kernel<<<NROWS, 128>>>();
    gemm_kernel<false><<<dim3(Dd / 64, NROWS / 64), 256>>>(outs, Dd, W_out, ol, Dd);
    rms_kernel<<<NROWS, 128>>>(rmsw, out);
}